// round 3
// baseline (speedup 1.0000x reference)
#include <cuda_runtime.h>

#define N_NODES 100000
#define N_EDGES 1600000
#define F 64

typedef unsigned long long ull;

// ---------------- scratch (static device globals; no allocation) ----------------
__device__ int   g_deg[N_NODES];
__device__ int   g_cursor[N_NODES];
__device__ int   g_row_ptr[N_NODES + 1];
__device__ int   g_csr_src[N_EDGES];
__device__ float g_mean[(size_t)N_NODES * F];
__device__ float g_h1[(size_t)N_NODES * F];
__device__ float g_sa[N_NODES];
__device__ float g_sb[N_NODES];

// ---------------- packed f32x2 helpers (Blackwell FFMA2) ----------------
__device__ __forceinline__ ull fma2(ull a, ull b, ull c) {
    ull d;
    asm("fma.rn.f32x2 %0, %1, %2, %3;" : "=l"(d) : "l"(a), "l"(b), "l"(c));
    return d;
}
__device__ __forceinline__ ull pack2(float x, float y) {
    ull r; asm("mov.b64 %0, {%1, %2};" : "=l"(r) : "f"(x), "f"(y)); return r;
}
__device__ __forceinline__ float hsum2(ull a) {
    float x, y; asm("mov.b64 {%0, %1}, %2;" : "=f"(x), "=f"(y) : "l"(a)); return x + y;
}

// ---------------- CSR build ----------------
__global__ void zero_kernel() {
    int i = blockIdx.x * blockDim.x + threadIdx.x;
    if (i < N_NODES) g_deg[i] = 0;
}

__global__ void hist_kernel(const int* __restrict__ ei) {
    int e4 = blockIdx.x * blockDim.x + threadIdx.x;
    if (e4 >= N_EDGES / 4) return;
    int4 d = __ldg((const int4*)(ei + N_EDGES) + e4);
    atomicAdd(&g_deg[d.x], 1);
    atomicAdd(&g_deg[d.y], 1);
    atomicAdd(&g_deg[d.z], 1);
    atomicAdd(&g_deg[d.w], 1);
}

// single-block exclusive scan of degrees -> row_ptr (also seeds cursor)
__global__ void scan_kernel() {
    __shared__ int sums[1024];
    const int t = threadIdx.x;
    const int CH = (N_NODES + 1023) / 1024;   // 98
    int begin = t * CH;
    int end = begin + CH; if (end > N_NODES) end = N_NODES;
    int s = 0;
    for (int i = begin; i < end; i++) s += g_deg[i];
    sums[t] = s;
    __syncthreads();
    for (int off = 1; off < 1024; off <<= 1) {
        int v = (t >= off) ? sums[t - off] : 0;
        __syncthreads();
        sums[t] += v;
        __syncthreads();
    }
    int run = (t == 0) ? 0 : sums[t - 1];
    for (int i = begin; i < end; i++) {
        g_row_ptr[i] = run;
        g_cursor[i]  = run;
        run += g_deg[i];
    }
    if (t == 1023) g_row_ptr[N_NODES] = sums[1023];
}

__global__ void fill_kernel(const int* __restrict__ ei) {
    int e4 = blockIdx.x * blockDim.x + threadIdx.x;
    if (e4 >= N_EDGES / 4) return;
    int4 s = __ldg((const int4*)ei + e4);
    int4 d = __ldg((const int4*)(ei + N_EDGES) + e4);
    g_csr_src[atomicAdd(&g_cursor[d.x], 1)] = s.x;
    g_csr_src[atomicAdd(&g_cursor[d.y], 1)] = s.y;
    g_csr_src[atomicAdd(&g_cursor[d.z], 1)] = s.z;
    g_csr_src[atomicAdd(&g_cursor[d.w], 1)] = s.w;
}

// ---------------- mean aggregation (CSR pull, 16 threads/node, MLP-4 unroll) ----------------
__global__ void agg_kernel(const float* __restrict__ x0, int layer) {
    const float* __restrict__ xin = (layer == 0) ? x0 : (const float*)g_h1;
    int gid  = blockIdx.x * blockDim.x + threadIdx.x;
    int node = gid >> 4;
    int lane = gid & 15;
    // grid is exactly N_NODES*16 threads; no tail divergence
    const unsigned hm = ((threadIdx.x & 31) < 16) ? 0x0000FFFFu : 0xFFFF0000u;

    int beg = g_row_ptr[node];
    int end = g_row_ptr[node + 1];
    float4 a0 = make_float4(0.f, 0.f, 0.f, 0.f);
    float4 a1 = make_float4(0.f, 0.f, 0.f, 0.f);
    float4 a2 = make_float4(0.f, 0.f, 0.f, 0.f);
    float4 a3 = make_float4(0.f, 0.f, 0.f, 0.f);

    const float4* __restrict__ x4 = (const float4*)xin;

    for (int base = beg; base < end; base += 16) {
        int my  = base + lane;
        int idx = (my < end) ? g_csr_src[my] : 0;
        int cnt = end - base; if (cnt > 16) cnt = 16;
        int t = 0;
        // 4 independent loads in flight per thread
        for (; t + 4 <= cnt; t += 4) {
            int s0 = __shfl_sync(hm, idx, t,     16);
            int s1 = __shfl_sync(hm, idx, t + 1, 16);
            int s2 = __shfl_sync(hm, idx, t + 2, 16);
            int s3 = __shfl_sync(hm, idx, t + 3, 16);
            float4 v0 = __ldg(x4 + (size_t)s0 * 16 + lane);
            float4 v1 = __ldg(x4 + (size_t)s1 * 16 + lane);
            float4 v2 = __ldg(x4 + (size_t)s2 * 16 + lane);
            float4 v3 = __ldg(x4 + (size_t)s3 * 16 + lane);
            a0.x += v0.x; a0.y += v0.y; a0.z += v0.z; a0.w += v0.w;
            a1.x += v1.x; a1.y += v1.y; a1.z += v1.z; a1.w += v1.w;
            a2.x += v2.x; a2.y += v2.y; a2.z += v2.z; a2.w += v2.w;
            a3.x += v3.x; a3.y += v3.y; a3.z += v3.z; a3.w += v3.w;
        }
        for (; t < cnt; t++) {
            int s = __shfl_sync(hm, idx, t, 16);
            float4 v = __ldg(x4 + (size_t)s * 16 + lane);
            a0.x += v.x; a0.y += v.y; a0.z += v.z; a0.w += v.w;
        }
    }
    float4 acc;
    acc.x = (a0.x + a1.x) + (a2.x + a3.x);
    acc.y = (a0.y + a1.y) + (a2.y + a3.y);
    acc.z = (a0.z + a1.z) + (a2.z + a3.z);
    acc.w = (a0.w + a1.w) + (a2.w + a3.w);
    float inv = (end > beg) ? 1.0f / (float)(end - beg) : 0.0f;
    acc.x *= inv; acc.y *= inv; acc.z *= inv; acc.w *= inv;
    ((float4*)g_mean)[node * 16 + lane] = acc;
}

// ---------------- SAGE transform: h = relu(mean @ Wl^T + b + x @ Wr^T) ----------------
// weights register-resident, one output feature per thread, 2 nodes per iteration,
// f32x2 packed FMA. For layer 1, fuses the edge-scorer halves:
//   sa[n] = h2[n] . Wlin[0:64],  sb[n] = h2[n] . Wlin[64:128]
__global__ void __launch_bounds__(256, 1) transform_kernel(
    const float* __restrict__ x0,
    const float* __restrict__ Wl, const float* __restrict__ bl,
    const float* __restrict__ Wr, const float* __restrict__ Wlin,
    int layer)
{
    const float* __restrict__ xin = (layer == 0) ? x0 : (const float*)g_h1;

    const int j = threadIdx.x & 63;   // output feature
    const int g = threadIdx.x >> 6;   // node-pair group within block (0..3)
    const int w = threadIdx.x >> 5;   // warp within block (0..7)
    const int lid = threadIdx.x & 31;

    ull wl[32], wr[32];
#pragma unroll
    for (int k = 0; k < 16; k++) {
        float4 a = __ldg((const float4*)Wl + j * 16 + k);
        float4 b = __ldg((const float4*)Wr + j * 16 + k);
        wl[2 * k]     = pack2(a.x, a.y);
        wl[2 * k + 1] = pack2(a.z, a.w);
        wr[2 * k]     = pack2(b.x, b.y);
        wr[2 * k + 1] = pack2(b.z, b.w);
    }
    const float bias = __ldg(bl + j);
    float wa = 0.f, wb = 0.f;
    if (layer == 1) { wa = __ldg(Wlin + j); wb = __ldg(Wlin + 64 + j); }

    __shared__ float red[8][4];   // [warp][paA,pbA,paB,pbB]

    for (int nA = blockIdx.x * 8 + g * 2; nA < N_NODES; nA += gridDim.x * 8) {
        const int nB = nA + 1;  // N_NODES even; nA even => nB < N_NODES
        const float4* mA = (const float4*)g_mean + (size_t)nA * 16;
        const float4* xA = (const float4*)xin   + (size_t)nA * 16;
        const float4* mB = (const float4*)g_mean + (size_t)nB * 16;
        const float4* xB = (const float4*)xin   + (size_t)nB * 16;

        ull aA0 = 0, aA1 = 0, aA2 = 0, aA3 = 0;
        ull aB0 = 0, aB1 = 0, aB2 = 0, aB3 = 0;
#pragma unroll
        for (int k = 0; k < 16; k++) {
            float4 mvA = __ldg(mA + k);
            float4 xvA = __ldg(xA + k);
            float4 mvB = __ldg(mB + k);
            float4 xvB = __ldg(xB + k);
            aA0 = fma2(wl[2 * k],     pack2(mvA.x, mvA.y), aA0);
            aA1 = fma2(wl[2 * k + 1], pack2(mvA.z, mvA.w), aA1);
            aA2 = fma2(wr[2 * k],     pack2(xvA.x, xvA.y), aA2);
            aA3 = fma2(wr[2 * k + 1], pack2(xvA.z, xvA.w), aA3);
            aB0 = fma2(wl[2 * k],     pack2(mvB.x, mvB.y), aB0);
            aB1 = fma2(wl[2 * k + 1], pack2(mvB.z, mvB.w), aB1);
            aB2 = fma2(wr[2 * k],     pack2(xvB.x, xvB.y), aB2);
            aB3 = fma2(wr[2 * k + 1], pack2(xvB.z, xvB.w), aB3);
        }
        float sA = fmaxf(hsum2(aA0) + hsum2(aA1) + hsum2(aA2) + hsum2(aA3) + bias, 0.f);
        float sB = fmaxf(hsum2(aB0) + hsum2(aB1) + hsum2(aB2) + hsum2(aB3) + bias, 0.f);

        if (layer == 0) {
            g_h1[(size_t)nA * 64 + j] = sA;
            g_h1[(size_t)nB * 64 + j] = sB;
        } else {
            // fused edge-scorer halves: reduce sA*wa, sA*wb, sB*wa, sB*wb over 64 j's
            float paA = sA * wa, pbA = sA * wb;
            float paB = sB * wa, pbB = sB * wb;
#pragma unroll
            for (int off = 16; off; off >>= 1) {
                paA += __shfl_down_sync(0xFFFFFFFFu, paA, off);
                pbA += __shfl_down_sync(0xFFFFFFFFu, pbA, off);
                paB += __shfl_down_sync(0xFFFFFFFFu, paB, off);
                pbB += __shfl_down_sync(0xFFFFFFFFu, pbB, off);
            }
            if (lid == 0) {
                red[w][0] = paA; red[w][1] = pbA;
                red[w][2] = paB; red[w][3] = pbB;
            }
            __syncthreads();
            if (threadIdx.x < 4) {       // one thread per group combines its 2 warps
                int gg = threadIdx.x;
                int n0 = nA - g * 2 + gg * 2;   // this group's nA
                if (n0 < N_NODES) {
                    g_sa[n0]     = red[2 * gg][0] + red[2 * gg + 1][0];
                    g_sb[n0]     = red[2 * gg][1] + red[2 * gg + 1][1];
                    g_sa[n0 + 1] = red[2 * gg][2] + red[2 * gg + 1][2];
                    g_sb[n0 + 1] = red[2 * gg][3] + red[2 * gg + 1][3];
                }
            }
            __syncthreads();
        }
    }
}

// ---------------- final edge scores (4 edges per thread) ----------------
__global__ void edge_kernel(const int* __restrict__ ei,
                            const float* __restrict__ blin,
                            float* __restrict__ out)
{
    int e4 = blockIdx.x * blockDim.x + threadIdx.x;
    if (e4 >= N_EDGES / 4) return;
    int4 s = __ldg((const int4*)ei + e4);
    int4 d = __ldg((const int4*)(ei + N_EDGES) + e4);
    float b = __ldg(blin);
    float4 r;
    r.x = g_sa[s.x] + g_sb[d.x] + b;
    r.y = g_sa[s.y] + g_sb[d.y] + b;
    r.z = g_sa[s.z] + g_sb[d.z] + b;
    r.w = g_sa[s.w] + g_sb[d.w] + b;
    ((float4*)out)[e4] = r;
}

// ---------------- launch ----------------
extern "C" void kernel_launch(void* const* d_in, const int* in_sizes, int n_in,
                              void* d_out, int out_size)
{
    const float* x    = (const float*)d_in[0];
    const int*   ei   = (const int*)  d_in[1];
    const float* W1l  = (const float*)d_in[2];
    const float* b1l  = (const float*)d_in[3];
    const float* W1r  = (const float*)d_in[4];
    const float* W2l  = (const float*)d_in[5];
    const float* b2l  = (const float*)d_in[6];
    const float* W2r  = (const float*)d_in[7];
    const float* Wlin = (const float*)d_in[8];
    const float* blin = (const float*)d_in[9];
    float* out = (float*)d_out;

    const int E4B = (N_EDGES / 4 + 255) / 256;

    zero_kernel<<<(N_NODES + 255) / 256, 256>>>();
    hist_kernel<<<E4B, 256>>>(ei);
    scan_kernel<<<1, 1024>>>();
    fill_kernel<<<E4B, 256>>>(ei);

    // layer 1
    agg_kernel<<<N_NODES * 16 / 256, 256>>>(x, 0);
    transform_kernel<<<152, 256>>>(x, W1l, b1l, W1r, Wlin, 0);

    // layer 2 (transform fuses edge-scorer halves; h2 never materialized)
    agg_kernel<<<N_NODES * 16 / 256, 256>>>(x, 1);
    transform_kernel<<<152, 256>>>(x, W2l, b2l, W2r, Wlin, 1);

    // edge scoring
    edge_kernel<<<E4B, 256>>>(ei, blin, out);
}

// round 4
// speedup vs baseline: 1.0301x; 1.0301x over previous
#include <cuda_runtime.h>

#define N_NODES 100000
#define N_EDGES 1600000
#define F 64

typedef unsigned long long ull;

// ---------------- scratch (static device globals; no allocation) ----------------
__device__ int   g_deg[N_NODES];
__device__ int   g_cursor[N_NODES];
__device__ int   g_row_ptr[N_NODES + 1];
__device__ int   g_csr_src[N_EDGES];
__device__ float g_mean[(size_t)N_NODES * F];
__device__ float g_h1[(size_t)N_NODES * F];
__device__ float g_h2[(size_t)N_NODES * F];
__device__ float g_sa[N_NODES];
__device__ float g_sb[N_NODES];

// ---------------- packed f32x2 helpers (Blackwell FFMA2) ----------------
__device__ __forceinline__ ull fma2(ull a, ull b, ull c) {
    ull d;
    asm("fma.rn.f32x2 %0, %1, %2, %3;" : "=l"(d) : "l"(a), "l"(b), "l"(c));
    return d;
}
__device__ __forceinline__ ull pack2(float x, float y) {
    ull r; asm("mov.b64 %0, {%1, %2};" : "=l"(r) : "f"(x), "f"(y)); return r;
}
__device__ __forceinline__ float hsum2(ull a) {
    float x, y; asm("mov.b64 {%0, %1}, %2;" : "=f"(x), "=f"(y) : "l"(a)); return x + y;
}

// ---------------- CSR build ----------------
__global__ void zero_kernel() {
    int i = blockIdx.x * blockDim.x + threadIdx.x;
    if (i < N_NODES) g_deg[i] = 0;
}

__global__ void hist_kernel(const int* __restrict__ ei) {
    int e4 = blockIdx.x * blockDim.x + threadIdx.x;
    if (e4 >= N_EDGES / 4) return;
    int4 d = __ldg((const int4*)(ei + N_EDGES) + e4);
    atomicAdd(&g_deg[d.x], 1);
    atomicAdd(&g_deg[d.y], 1);
    atomicAdd(&g_deg[d.z], 1);
    atomicAdd(&g_deg[d.w], 1);
}

// single-block exclusive scan of degrees -> row_ptr (also seeds cursor)
__global__ void scan_kernel() {
    __shared__ int sums[1024];
    const int t = threadIdx.x;
    const int CH = (N_NODES + 1023) / 1024;   // 98
    int begin = t * CH;
    int end = begin + CH; if (end > N_NODES) end = N_NODES;
    int s = 0;
    for (int i = begin; i < end; i++) s += g_deg[i];
    sums[t] = s;
    __syncthreads();
    for (int off = 1; off < 1024; off <<= 1) {
        int v = (t >= off) ? sums[t - off] : 0;
        __syncthreads();
        sums[t] += v;
        __syncthreads();
    }
    int run = (t == 0) ? 0 : sums[t - 1];
    for (int i = begin; i < end; i++) {
        g_row_ptr[i] = run;
        g_cursor[i]  = run;
        run += g_deg[i];
    }
    if (t == 1023) g_row_ptr[N_NODES] = sums[1023];
}

__global__ void fill_kernel(const int* __restrict__ ei) {
    int e4 = blockIdx.x * blockDim.x + threadIdx.x;
    if (e4 >= N_EDGES / 4) return;
    int4 s = __ldg((const int4*)ei + e4);
    int4 d = __ldg((const int4*)(ei + N_EDGES) + e4);
    g_csr_src[atomicAdd(&g_cursor[d.x], 1)] = s.x;
    g_csr_src[atomicAdd(&g_cursor[d.y], 1)] = s.y;
    g_csr_src[atomicAdd(&g_cursor[d.z], 1)] = s.z;
    g_csr_src[atomicAdd(&g_cursor[d.w], 1)] = s.w;
}

// ---------------- mean aggregation (CSR pull, 16 threads/node, MLP-4 unroll) ----------------
__global__ void agg_kernel(const float* __restrict__ x0, int layer) {
    const float* __restrict__ xin = (layer == 0) ? x0 : (const float*)g_h1;
    int gid  = blockIdx.x * blockDim.x + threadIdx.x;
    int node = gid >> 4;
    int lane = gid & 15;
    const unsigned hm = ((threadIdx.x & 31) < 16) ? 0x0000FFFFu : 0xFFFF0000u;

    int beg = g_row_ptr[node];
    int end = g_row_ptr[node + 1];
    float4 a0 = make_float4(0.f, 0.f, 0.f, 0.f);
    float4 a1 = make_float4(0.f, 0.f, 0.f, 0.f);
    float4 a2 = make_float4(0.f, 0.f, 0.f, 0.f);
    float4 a3 = make_float4(0.f, 0.f, 0.f, 0.f);

    const float4* __restrict__ x4 = (const float4*)xin;

    for (int base = beg; base < end; base += 16) {
        int my  = base + lane;
        int idx = (my < end) ? g_csr_src[my] : 0;
        int cnt = end - base; if (cnt > 16) cnt = 16;
        int t = 0;
        for (; t + 4 <= cnt; t += 4) {
            int s0 = __shfl_sync(hm, idx, t,     16);
            int s1 = __shfl_sync(hm, idx, t + 1, 16);
            int s2 = __shfl_sync(hm, idx, t + 2, 16);
            int s3 = __shfl_sync(hm, idx, t + 3, 16);
            float4 v0 = __ldg(x4 + (size_t)s0 * 16 + lane);
            float4 v1 = __ldg(x4 + (size_t)s1 * 16 + lane);
            float4 v2 = __ldg(x4 + (size_t)s2 * 16 + lane);
            float4 v3 = __ldg(x4 + (size_t)s3 * 16 + lane);
            a0.x += v0.x; a0.y += v0.y; a0.z += v0.z; a0.w += v0.w;
            a1.x += v1.x; a1.y += v1.y; a1.z += v1.z; a1.w += v1.w;
            a2.x += v2.x; a2.y += v2.y; a2.z += v2.z; a2.w += v2.w;
            a3.x += v3.x; a3.y += v3.y; a3.z += v3.z; a3.w += v3.w;
        }
        for (; t < cnt; t++) {
            int s = __shfl_sync(hm, idx, t, 16);
            float4 v = __ldg(x4 + (size_t)s * 16 + lane);
            a0.x += v.x; a0.y += v.y; a0.z += v.z; a0.w += v.w;
        }
    }
    float4 acc;
    acc.x = (a0.x + a1.x) + (a2.x + a3.x);
    acc.y = (a0.y + a1.y) + (a2.y + a3.y);
    acc.z = (a0.z + a1.z) + (a2.z + a3.z);
    acc.w = (a0.w + a1.w) + (a2.w + a3.w);
    float inv = (end > beg) ? 1.0f / (float)(end - beg) : 0.0f;
    acc.x *= inv; acc.y *= inv; acc.z *= inv; acc.w *= inv;
    ((float4*)g_mean)[node * 16 + lane] = acc;
}

// ---------------- SAGE transform: h = relu(mean @ Wl^T + b + x @ Wr^T) ----------------
// Weights register-resident (packed f32x2), one output feature per thread.
// Feature rows loaded as ulonglong2 so fma2 operands are already 64-bit pairs:
// NO per-element packing MOVs in the hot loop. No barriers in the loop.
__global__ void __launch_bounds__(256, 1) transform_kernel(
    const float* __restrict__ xin,
    const float* __restrict__ Wl, const float* __restrict__ bl,
    const float* __restrict__ Wr, float* __restrict__ hout)
{
    const int j = threadIdx.x & 63;   // output feature
    const int g = threadIdx.x >> 6;   // node group within block (0..3)

    ull wl[32], wr[32];
#pragma unroll
    for (int k = 0; k < 16; k++) {
        float4 a = __ldg((const float4*)Wl + j * 16 + k);
        float4 b = __ldg((const float4*)Wr + j * 16 + k);
        wl[2 * k]     = pack2(a.x, a.y);
        wl[2 * k + 1] = pack2(a.z, a.w);
        wr[2 * k]     = pack2(b.x, b.y);
        wr[2 * k + 1] = pack2(b.z, b.w);
    }
    const float bias = __ldg(bl + j);

    const ulonglong2* __restrict__ m2b = (const ulonglong2*)g_mean;
    const ulonglong2* __restrict__ x2b = (const ulonglong2*)xin;

    for (int n = blockIdx.x * 4 + g; n < N_NODES; n += gridDim.x * 4) {
        const ulonglong2* m2 = m2b + (size_t)n * 16;
        const ulonglong2* x2 = x2b + (size_t)n * 16;
        ull a0 = 0, a1 = 0, a2 = 0, a3 = 0;
#pragma unroll
        for (int k = 0; k < 16; k++) {
            ulonglong2 mv = __ldg(m2 + k);   // 4 floats of mean row
            ulonglong2 xv = __ldg(x2 + k);   // 4 floats of x row
            a0 = fma2(wl[2 * k],     mv.x, a0);
            a1 = fma2(wl[2 * k + 1], mv.y, a1);
            a2 = fma2(wr[2 * k],     xv.x, a2);
            a3 = fma2(wr[2 * k + 1], xv.y, a3);
        }
        float s = hsum2(a0) + hsum2(a1) + hsum2(a2) + hsum2(a3) + bias;
        hout[(size_t)n * 64 + j] = fmaxf(s, 0.0f);
    }
}

// ---------------- per-node edge-score halves: sa = h2·Wlin[:64], sb = h2·Wlin[64:] ----------------
__global__ void sab_kernel(const float* __restrict__ Wlin) {
    int n = blockIdx.x * blockDim.x + threadIdx.x;
    if (n >= N_NODES) return;
    const float4* h4 = (const float4*)g_h2 + (size_t)n * 16;
    float sa = 0.f, sb = 0.f;
#pragma unroll
    for (int k = 0; k < 16; k++) {
        float4 h  = __ldg(h4 + k);
        float4 wa = __ldg((const float4*)Wlin + k);
        float4 wb = __ldg((const float4*)Wlin + 16 + k);
        sa += h.x * wa.x + h.y * wa.y + h.z * wa.z + h.w * wa.w;
        sb += h.x * wb.x + h.y * wb.y + h.z * wb.z + h.w * wb.w;
    }
    g_sa[n] = sa;
    g_sb[n] = sb;
}

// ---------------- final edge scores (4 edges per thread) ----------------
__global__ void edge_kernel(const int* __restrict__ ei,
                            const float* __restrict__ blin,
                            float* __restrict__ out)
{
    int e4 = blockIdx.x * blockDim.x + threadIdx.x;
    if (e4 >= N_EDGES / 4) return;
    int4 s = __ldg((const int4*)ei + e4);
    int4 d = __ldg((const int4*)(ei + N_EDGES) + e4);
    float b = __ldg(blin);
    float4 r;
    r.x = g_sa[s.x] + g_sb[d.x] + b;
    r.y = g_sa[s.y] + g_sb[d.y] + b;
    r.z = g_sa[s.z] + g_sb[d.z] + b;
    r.w = g_sa[s.w] + g_sb[d.w] + b;
    ((float4*)out)[e4] = r;
}

// ---------------- launch ----------------
extern "C" void kernel_launch(void* const* d_in, const int* in_sizes, int n_in,
                              void* d_out, int out_size)
{
    const float* x    = (const float*)d_in[0];
    const int*   ei   = (const int*)  d_in[1];
    const float* W1l  = (const float*)d_in[2];
    const float* b1l  = (const float*)d_in[3];
    const float* W1r  = (const float*)d_in[4];
    const float* W2l  = (const float*)d_in[5];
    const float* b2l  = (const float*)d_in[6];
    const float* W2r  = (const float*)d_in[7];
    const float* Wlin = (const float*)d_in[8];
    const float* blin = (const float*)d_in[9];
    float* out = (float*)d_out;

    const int E4B = (N_EDGES / 4 + 255) / 256;

    // device-global scratch pointers (resolved host-side once per launch)
    float* p_h1;  cudaGetSymbolAddress((void**)&p_h1, g_h1);
    float* p_h2;  cudaGetSymbolAddress((void**)&p_h2, g_h2);

    zero_kernel<<<(N_NODES + 255) / 256, 256>>>();
    hist_kernel<<<E4B, 256>>>(ei);
    scan_kernel<<<1, 1024>>>();
    fill_kernel<<<E4B, 256>>>(ei);

    // layer 1
    agg_kernel<<<N_NODES * 16 / 256, 256>>>(x, 0);
    transform_kernel<<<152, 256>>>(x, W1l, b1l, W1r, p_h1);

    // layer 2
    agg_kernel<<<N_NODES * 16 / 256, 256>>>(x, 1);
    transform_kernel<<<152, 256>>>(p_h1, W2l, b2l, W2r, p_h2);

    // edge scoring
    sab_kernel<<<(N_NODES + 255) / 256, 256>>>(Wlin);
    edge_kernel<<<E4B, 256>>>(ei, blin, out);
}

// round 6
// speedup vs baseline: 1.0447x; 1.0142x over previous
#include <cuda_runtime.h>

#define N_NODES 100000
#define N_EDGES 1600000
#define F 64

typedef unsigned long long ull;

// ---------------- scratch (static device globals; no allocation) ----------------
__device__ int   g_deg[N_NODES];
__device__ int   g_cursor[N_NODES];
__device__ int   g_row_ptr[N_NODES + 1];
__device__ int   g_csr_src[N_EDGES];
__device__ float g_mean[(size_t)N_NODES * F];
__device__ float g_h1[(size_t)N_NODES * F];
__device__ float g_h2[(size_t)N_NODES * F];
__device__ float g_sa[N_NODES];
__device__ float g_sb[N_NODES];

// ---------------- packed f32x2 helpers (Blackwell FFMA2) ----------------
__device__ __forceinline__ ull fma2(ull a, ull b, ull c) {
    ull d;
    asm("fma.rn.f32x2 %0, %1, %2, %3;" : "=l"(d) : "l"(a), "l"(b), "l"(c));
    return d;
}
__device__ __forceinline__ ull pack2(float x, float y) {
    ull r; asm("mov.b64 %0, {%1, %2};" : "=l"(r) : "f"(x), "f"(y)); return r;
}
__device__ __forceinline__ float hsum2(ull a) {
    float x, y; asm("mov.b64 {%0, %1}, %2;" : "=f"(x), "=f"(y) : "l"(a)); return x + y;
}

// ---------------- CSR build ----------------
__global__ void hist_kernel(const int* __restrict__ ei) {
    int e4 = blockIdx.x * blockDim.x + threadIdx.x;
    if (e4 >= N_EDGES / 4) return;
    int4 d = __ldg((const int4*)(ei + N_EDGES) + e4);
    atomicAdd(&g_deg[d.x], 1);
    atomicAdd(&g_deg[d.y], 1);
    atomicAdd(&g_deg[d.z], 1);
    atomicAdd(&g_deg[d.w], 1);
}

// single-block exclusive scan of degrees -> row_ptr (also seeds cursor)
__global__ void scan_kernel() {
    __shared__ int sums[1024];
    const int t = threadIdx.x;
    const int CH = (N_NODES + 1023) / 1024;   // 98
    int begin = t * CH;
    int end = begin + CH; if (end > N_NODES) end = N_NODES;
    int s = 0;
    for (int i = begin; i < end; i++) s += g_deg[i];
    sums[t] = s;
    __syncthreads();
    for (int off = 1; off < 1024; off <<= 1) {
        int v = (t >= off) ? sums[t - off] : 0;
        __syncthreads();
        sums[t] += v;
        __syncthreads();
    }
    int run = (t == 0) ? 0 : sums[t - 1];
    for (int i = begin; i < end; i++) {
        g_row_ptr[i] = run;
        g_cursor[i]  = run;
        run += g_deg[i];
    }
    if (t == 1023) g_row_ptr[N_NODES] = sums[1023];
}

__global__ void fill_kernel(const int* __restrict__ ei) {
    int e4 = blockIdx.x * blockDim.x + threadIdx.x;
    if (e4 >= N_EDGES / 4) return;
    int4 s = __ldg((const int4*)ei + e4);
    int4 d = __ldg((const int4*)(ei + N_EDGES) + e4);
    g_csr_src[atomicAdd(&g_cursor[d.x], 1)] = s.x;
    g_csr_src[atomicAdd(&g_cursor[d.y], 1)] = s.y;
    g_csr_src[atomicAdd(&g_cursor[d.z], 1)] = s.z;
    g_csr_src[atomicAdd(&g_cursor[d.w], 1)] = s.w;
}

// ---------------- mean aggregation ----------------
// Warp-per-node, 32 lanes x float2 (one LDG.64 warp-instr per edge).
// Neighbor indices fetched by broadcast __ldg (no shfl, no divergence),
// 8 independent index loads + 8 independent feature loads per step (MLP-8).
__global__ void agg_kernel(const float* __restrict__ xin) {
    int warp = (blockIdx.x * blockDim.x + threadIdx.x) >> 5;
    int lane = threadIdx.x & 31;
    if (warp >= N_NODES) return;          // grid sized exactly

    const int beg = g_row_ptr[warp];
    const int end = g_row_ptr[warp + 1];

    const float2* __restrict__ x2 = (const float2*)xin;

    float2 a0 = make_float2(0.f, 0.f);
    float2 a1 = make_float2(0.f, 0.f);
    float2 a2 = make_float2(0.f, 0.f);
    float2 a3 = make_float2(0.f, 0.f);

    for (int base = beg; base < end; base += 8) {
        int s[8];
#pragma unroll
        for (int u = 0; u < 8; u++)
            s[u] = (base + u < end) ? __ldg(g_csr_src + base + u) : -1;

        float2 v[8];
#pragma unroll
        for (int u = 0; u < 8; u++)
            v[u] = (s[u] >= 0) ? __ldg(x2 + (size_t)s[u] * 32 + lane)
                               : make_float2(0.f, 0.f);

        a0.x += v[0].x + v[4].x; a0.y += v[0].y + v[4].y;
        a1.x += v[1].x + v[5].x; a1.y += v[1].y + v[5].y;
        a2.x += v[2].x + v[6].x; a2.y += v[2].y + v[6].y;
        a3.x += v[3].x + v[7].x; a3.y += v[3].y + v[7].y;
    }

    float2 acc;
    acc.x = (a0.x + a1.x) + (a2.x + a3.x);
    acc.y = (a0.y + a1.y) + (a2.y + a3.y);
    float inv = (end > beg) ? 1.0f / (float)(end - beg) : 0.0f;
    acc.x *= inv; acc.y *= inv;
    ((float2*)g_mean)[(size_t)warp * 32 + lane] = acc;
}

// ---------------- SAGE transform: h = relu(mean @ Wl^T + b + x @ Wr^T) ----------------
// Weights register-resident (packed f32x2), one output feature per thread.
// Rows loaded as ulonglong2 -> fma2 operands born as 64-bit pairs (no pack MOVs).
__global__ void __launch_bounds__(256, 1) transform_kernel(
    const float* __restrict__ xin,
    const float* __restrict__ Wl, const float* __restrict__ bl,
    const float* __restrict__ Wr, float* __restrict__ hout)
{
    const int j = threadIdx.x & 63;   // output feature
    const int g = threadIdx.x >> 6;   // node group within block (0..3)

    ull wl[32], wr[32];
#pragma unroll
    for (int k = 0; k < 16; k++) {
        float4 a = __ldg((const float4*)Wl + j * 16 + k);
        float4 b = __ldg((const float4*)Wr + j * 16 + k);
        wl[2 * k]     = pack2(a.x, a.y);
        wl[2 * k + 1] = pack2(a.z, a.w);
        wr[2 * k]     = pack2(b.x, b.y);
        wr[2 * k + 1] = pack2(b.z, b.w);
    }
    const float bias = __ldg(bl + j);

    const ulonglong2* __restrict__ m2b = (const ulonglong2*)g_mean;
    const ulonglong2* __restrict__ x2b = (const ulonglong2*)xin;

    for (int n = blockIdx.x * 4 + g; n < N_NODES; n += gridDim.x * 4) {
        const ulonglong2* m2 = m2b + (size_t)n * 16;
        const ulonglong2* x2 = x2b + (size_t)n * 16;
        ull a0 = 0, a1 = 0, a2 = 0, a3 = 0;
#pragma unroll
        for (int k = 0; k < 16; k++) {
            ulonglong2 mv = __ldg(m2 + k);
            ulonglong2 xv = __ldg(x2 + k);
            a0 = fma2(wl[2 * k],     mv.x, a0);
            a1 = fma2(wl[2 * k + 1], mv.y, a1);
            a2 = fma2(wr[2 * k],     xv.x, a2);
            a3 = fma2(wr[2 * k + 1], xv.y, a3);
        }
        float s = hsum2(a0) + hsum2(a1) + hsum2(a2) + hsum2(a3) + bias;
        hout[(size_t)n * 64 + j] = fmaxf(s, 0.0f);
    }
}

// ---------------- per-node edge-score halves ----------------
__global__ void sab_kernel(const float* __restrict__ Wlin) {
    int n = blockIdx.x * blockDim.x + threadIdx.x;
    if (n >= N_NODES) return;
    const float4* h4 = (const float4*)g_h2 + (size_t)n * 16;
    float sa = 0.f, sb = 0.f;
#pragma unroll
    for (int k = 0; k < 16; k++) {
        float4 h  = __ldg(h4 + k);
        float4 wa = __ldg((const float4*)Wlin + k);
        float4 wb = __ldg((const float4*)Wlin + 16 + k);
        sa += h.x * wa.x + h.y * wa.y + h.z * wa.z + h.w * wa.w;
        sb += h.x * wb.x + h.y * wb.y + h.z * wb.z + h.w * wb.w;
    }
    g_sa[n] = sa;
    g_sb[n] = sb;
}

// ---------------- final edge scores (4 edges per thread) ----------------
__global__ void edge_kernel(const int* __restrict__ ei,
                            const float* __restrict__ blin,
                            float* __restrict__ out)
{
    int e4 = blockIdx.x * blockDim.x + threadIdx.x;
    if (e4 >= N_EDGES / 4) return;
    int4 s = __ldg((const int4*)ei + e4);
    int4 d = __ldg((const int4*)(ei + N_EDGES) + e4);
    float b = __ldg(blin);
    float4 r;
    r.x = g_sa[s.x] + g_sb[d.x] + b;
    r.y = g_sa[s.y] + g_sb[d.y] + b;
    r.z = g_sa[s.z] + g_sb[d.z] + b;
    r.w = g_sa[s.w] + g_sb[d.w] + b;
    ((float4*)out)[e4] = r;
}

// ---------------- launch ----------------
extern "C" void kernel_launch(void* const* d_in, const int* in_sizes, int n_in,
                              void* d_out, int out_size)
{
    const float* x    = (const float*)d_in[0];
    const int*   ei   = (const int*)  d_in[1];
    const float* W1l  = (const float*)d_in[2];
    const float* b1l  = (const float*)d_in[3];
    const float* W1r  = (const float*)d_in[4];
    const float* W2l  = (const float*)d_in[5];
    const float* b2l  = (const float*)d_in[6];
    const float* W2r  = (const float*)d_in[7];
    const float* Wlin = (const float*)d_in[8];
    const float* blin = (const float*)d_in[9];
    float* out = (float*)d_out;

    const int E4B = (N_EDGES / 4 + 255) / 256;

    float* p_h1;  cudaGetSymbolAddress((void**)&p_h1, g_h1);
    float* p_h2;  cudaGetSymbolAddress((void**)&p_h2, g_h2);
    int*   p_deg; cudaGetSymbolAddress((void**)&p_deg, g_deg);

    // memset node (not a kernel launch): zeroes degree counters.
    cudaMemsetAsync(p_deg, 0, N_NODES * sizeof(int), 0);

    hist_kernel<<<E4B, 256>>>(ei);              // kernel 0
    scan_kernel<<<1, 1024>>>();                 // kernel 1
    fill_kernel<<<E4B, 256>>>(ei);              // kernel 2

    // layer 1   (agg now sits in the profiled launch slot)
    agg_kernel<<<N_NODES * 32 / 256, 256>>>(x);               // kernel 3
    transform_kernel<<<152, 256>>>(x, W1l, b1l, W1r, p_h1);   // kernel 4

    // layer 2
    agg_kernel<<<N_NODES * 32 / 256, 256>>>(p_h1);            // kernel 5
    transform_kernel<<<152, 256>>>(p_h1, W2l, b2l, W2r, p_h2);// kernel 6

    // edge scoring
    sab_kernel<<<(N_NODES + 255) / 256, 256>>>(Wlin);         // kernel 7
    edge_kernel<<<E4B, 256>>>(ei, blin, out);                 // kernel 8
}

// round 7
// speedup vs baseline: 1.4871x; 1.4234x over previous
#include <cuda_runtime.h>

#define N_NODES 100000
#define N_EDGES 1600000
#define F 64
#define NTILES ((N_NODES + 1023) / 1024)   // 98

typedef unsigned long long ull;

// ---------------- scratch (static device globals; no allocation) ----------------
__device__ int   g_deg[N_NODES];
__device__ int   g_cursor[N_NODES];
__device__ int   g_row_ptr[N_NODES + 1];
__device__ int   g_csr_src[N_EDGES];
__device__ int   g_tile_sum[NTILES];
__device__ int   g_tile_off[NTILES];
__device__ float g_mean[(size_t)N_NODES * F];
__device__ float g_h1[(size_t)N_NODES * F];
__device__ float g_h2[(size_t)N_NODES * F];
__device__ float g_sa[N_NODES];
__device__ float g_sb[N_NODES];

// ---------------- packed f32x2 helpers (Blackwell FFMA2) ----------------
__device__ __forceinline__ ull fma2(ull a, ull b, ull c) {
    ull d;
    asm("fma.rn.f32x2 %0, %1, %2, %3;" : "=l"(d) : "l"(a), "l"(b), "l"(c));
    return d;
}
__device__ __forceinline__ ull pack2(float x, float y) {
    ull r; asm("mov.b64 %0, {%1, %2};" : "=l"(r) : "f"(x), "f"(y)); return r;
}
__device__ __forceinline__ float hsum2(ull a) {
    float x, y; asm("mov.b64 {%0, %1}, %2;" : "=f"(x), "=f"(y) : "l"(a)); return x + y;
}

// ---------------- CSR build ----------------
__global__ void hist_kernel(const int* __restrict__ ei) {
    int e4 = blockIdx.x * blockDim.x + threadIdx.x;
    if (e4 >= N_EDGES / 4) return;
    int4 d = __ldg((const int4*)(ei + N_EDGES) + e4);
    atomicAdd(&g_deg[d.x], 1);
    atomicAdd(&g_deg[d.y], 1);
    atomicAdd(&g_deg[d.z], 1);
    atomicAdd(&g_deg[d.w], 1);
}

// Phase A: coalesced per-tile (1024) reduction of degrees.
__global__ void scanA_kernel() {
    __shared__ int wsum[32];
    int t = threadIdx.x, b = blockIdx.x;
    int i = b * 1024 + t;
    int v = (i < N_NODES) ? g_deg[i] : 0;
#pragma unroll
    for (int off = 16; off; off >>= 1)
        v += __shfl_down_sync(0xFFFFFFFFu, v, off);
    if ((t & 31) == 0) wsum[t >> 5] = v;
    __syncthreads();
    if (t < 32) {
        int s = wsum[t];
#pragma unroll
        for (int off = 16; off; off >>= 1)
            s += __shfl_down_sync(0xFFFFFFFFu, s, off);
        if (t == 0) g_tile_sum[b] = s;
    }
}

// Phase B: tiny single-block exclusive scan of the 98 tile sums.
__global__ void scanB_kernel() {
    __shared__ int sh[NTILES];
    int t = threadIdx.x;
    if (t < NTILES) sh[t] = g_tile_sum[t];
    __syncthreads();
    if (t == 0) {
        int run = 0;
        for (int i = 0; i < NTILES; i++) { int v = sh[i]; sh[i] = run; run += v; }
        g_row_ptr[N_NODES] = run;
    }
    __syncthreads();
    if (t < NTILES) g_tile_off[t] = sh[t];
}

// Phase C: coalesced block-wide exclusive scan + tile offset -> row_ptr, cursor.
__global__ void scanC_kernel() {
    __shared__ int wsum[32];
    int t = threadIdx.x, b = blockIdx.x;
    int i = b * 1024 + t;
    int v = (i < N_NODES) ? g_deg[i] : 0;
    int lane = t & 31, w = t >> 5;
    int x = v;
#pragma unroll
    for (int off = 1; off < 32; off <<= 1) {
        int y = __shfl_up_sync(0xFFFFFFFFu, x, off);
        if (lane >= off) x += y;
    }
    if (lane == 31) wsum[w] = x;
    __syncthreads();
    if (t < 32) {
        int s = wsum[t];
#pragma unroll
        for (int off = 1; off < 32; off <<= 1) {
            int y = __shfl_up_sync(0xFFFFFFFFu, s, off);
            if (t >= off) s += y;
        }
        wsum[t] = s;
    }
    __syncthreads();
    int base = g_tile_off[b] + (w ? wsum[w - 1] : 0);
    int excl = base + x - v;
    if (i < N_NODES) { g_row_ptr[i] = excl; g_cursor[i] = excl; }
}

__global__ void fill_kernel(const int* __restrict__ ei) {
    int e4 = blockIdx.x * blockDim.x + threadIdx.x;
    if (e4 >= N_EDGES / 4) return;
    int4 s = __ldg((const int4*)ei + e4);
    int4 d = __ldg((const int4*)(ei + N_EDGES) + e4);
    g_csr_src[atomicAdd(&g_cursor[d.x], 1)] = s.x;
    g_csr_src[atomicAdd(&g_cursor[d.y], 1)] = s.y;
    g_csr_src[atomicAdd(&g_cursor[d.z], 1)] = s.z;
    g_csr_src[atomicAdd(&g_cursor[d.w], 1)] = s.w;
}

// ---------------- mean aggregation ----------------
// Warp-per-node, 32 lanes x float2; broadcast index loads; MLP-8.
__global__ void agg_kernel(const float* __restrict__ xin) {
    int warp = (blockIdx.x * blockDim.x + threadIdx.x) >> 5;
    int lane = threadIdx.x & 31;
    if (warp >= N_NODES) return;

    const int beg = g_row_ptr[warp];
    const int end = g_row_ptr[warp + 1];

    const float2* __restrict__ x2 = (const float2*)xin;

    float2 a0 = make_float2(0.f, 0.f);
    float2 a1 = make_float2(0.f, 0.f);
    float2 a2 = make_float2(0.f, 0.f);
    float2 a3 = make_float2(0.f, 0.f);

    for (int base = beg; base < end; base += 8) {
        int s[8];
#pragma unroll
        for (int u = 0; u < 8; u++)
            s[u] = (base + u < end) ? __ldg(g_csr_src + base + u) : -1;

        float2 v[8];
#pragma unroll
        for (int u = 0; u < 8; u++)
            v[u] = (s[u] >= 0) ? __ldg(x2 + (size_t)s[u] * 32 + lane)
                               : make_float2(0.f, 0.f);

        a0.x += v[0].x + v[4].x; a0.y += v[0].y + v[4].y;
        a1.x += v[1].x + v[5].x; a1.y += v[1].y + v[5].y;
        a2.x += v[2].x + v[6].x; a2.y += v[2].y + v[6].y;
        a3.x += v[3].x + v[7].x; a3.y += v[3].y + v[7].y;
    }

    float2 acc;
    acc.x = (a0.x + a1.x) + (a2.x + a3.x);
    acc.y = (a0.y + a1.y) + (a2.y + a3.y);
    float inv = (end > beg) ? 1.0f / (float)(end - beg) : 0.0f;
    acc.x *= inv; acc.y *= inv;
    ((float2*)g_mean)[(size_t)warp * 32 + lane] = acc;
}

// ---------------- SAGE transform: h = relu(mean @ Wl^T + b + x @ Wr^T) ----------------
__global__ void __launch_bounds__(256, 1) transform_kernel(
    const float* __restrict__ xin,
    const float* __restrict__ Wl, const float* __restrict__ bl,
    const float* __restrict__ Wr, float* __restrict__ hout)
{
    const int j = threadIdx.x & 63;
    const int g = threadIdx.x >> 6;

    ull wl[32], wr[32];
#pragma unroll
    for (int k = 0; k < 16; k++) {
        float4 a = __ldg((const float4*)Wl + j * 16 + k);
        float4 b = __ldg((const float4*)Wr + j * 16 + k);
        wl[2 * k]     = pack2(a.x, a.y);
        wl[2 * k + 1] = pack2(a.z, a.w);
        wr[2 * k]     = pack2(b.x, b.y);
        wr[2 * k + 1] = pack2(b.z, b.w);
    }
    const float bias = __ldg(bl + j);

    const ulonglong2* __restrict__ m2b = (const ulonglong2*)g_mean;
    const ulonglong2* __restrict__ x2b = (const ulonglong2*)xin;

    for (int n = blockIdx.x * 4 + g; n < N_NODES; n += gridDim.x * 4) {
        const ulonglong2* m2 = m2b + (size_t)n * 16;
        const ulonglong2* x2 = x2b + (size_t)n * 16;
        ull a0 = 0, a1 = 0, a2 = 0, a3 = 0;
#pragma unroll
        for (int k = 0; k < 16; k++) {
            ulonglong2 mv = __ldg(m2 + k);
            ulonglong2 xv = __ldg(x2 + k);
            a0 = fma2(wl[2 * k],     mv.x, a0);
            a1 = fma2(wl[2 * k + 1], mv.y, a1);
            a2 = fma2(wr[2 * k],     xv.x, a2);
            a3 = fma2(wr[2 * k + 1], xv.y, a3);
        }
        float s = hsum2(a0) + hsum2(a1) + hsum2(a2) + hsum2(a3) + bias;
        hout[(size_t)n * 64 + j] = fmaxf(s, 0.0f);
    }
}

// ---------------- per-node edge-score halves ----------------
__global__ void sab_kernel(const float* __restrict__ Wlin) {
    int n = blockIdx.x * blockDim.x + threadIdx.x;
    if (n >= N_NODES) return;
    const float4* h4 = (const float4*)g_h2 + (size_t)n * 16;
    float sa = 0.f, sb = 0.f;
#pragma unroll
    for (int k = 0; k < 16; k++) {
        float4 h  = __ldg(h4 + k);
        float4 wa = __ldg((const float4*)Wlin + k);
        float4 wb = __ldg((const float4*)Wlin + 16 + k);
        sa += h.x * wa.x + h.y * wa.y + h.z * wa.z + h.w * wa.w;
        sb += h.x * wb.x + h.y * wb.y + h.z * wb.z + h.w * wb.w;
    }
    g_sa[n] = sa;
    g_sb[n] = sb;
}

// ---------------- final edge scores (4 edges per thread) ----------------
__global__ void edge_kernel(const int* __restrict__ ei,
                            const float* __restrict__ blin,
                            float* __restrict__ out)
{
    int e4 = blockIdx.x * blockDim.x + threadIdx.x;
    if (e4 >= N_EDGES / 4) return;
    int4 s = __ldg((const int4*)ei + e4);
    int4 d = __ldg((const int4*)(ei + N_EDGES) + e4);
    float b = __ldg(blin);
    float4 r;
    r.x = g_sa[s.x] + g_sb[d.x] + b;
    r.y = g_sa[s.y] + g_sb[d.y] + b;
    r.z = g_sa[s.z] + g_sb[d.z] + b;
    r.w = g_sa[s.w] + g_sb[d.w] + b;
    ((float4*)out)[e4] = r;
}

// ---------------- launch ----------------
extern "C" void kernel_launch(void* const* d_in, const int* in_sizes, int n_in,
                              void* d_out, int out_size)
{
    const float* x    = (const float*)d_in[0];
    const int*   ei   = (const int*)  d_in[1];
    const float* W1l  = (const float*)d_in[2];
    const float* b1l  = (const float*)d_in[3];
    const float* W1r  = (const float*)d_in[4];
    const float* W2l  = (const float*)d_in[5];
    const float* b2l  = (const float*)d_in[6];
    const float* W2r  = (const float*)d_in[7];
    const float* Wlin = (const float*)d_in[8];
    const float* blin = (const float*)d_in[9];
    float* out = (float*)d_out;

    const int E4B = (N_EDGES / 4 + 255) / 256;

    float* p_h1;  cudaGetSymbolAddress((void**)&p_h1, g_h1);
    float* p_h2;  cudaGetSymbolAddress((void**)&p_h2, g_h2);
    int*   p_deg; cudaGetSymbolAddress((void**)&p_deg, g_deg);

    cudaMemsetAsync(p_deg, 0, N_NODES * sizeof(int), 0);   // memset node, not a kernel

    hist_kernel<<<E4B, 256>>>(ei);     // kernel 0
    scanA_kernel<<<NTILES, 1024>>>();  // kernel 1
    scanB_kernel<<<1, 128>>>();        // kernel 2
    scanC_kernel<<<NTILES, 1024>>>();  // kernel 3
    fill_kernel<<<E4B, 256>>>(ei);     // kernel 4

    // layer 1 (agg sits in ncu's -s 5 capture slot)
    agg_kernel<<<N_NODES * 32 / 256, 256>>>(x);                 // kernel 5
    transform_kernel<<<152, 256>>>(x, W1l, b1l, W1r, p_h1);     // kernel 6

    // layer 2
    agg_kernel<<<N_NODES * 32 / 256, 256>>>(p_h1);              // kernel 7
    transform_kernel<<<152, 256>>>(p_h1, W2l, b2l, W2r, p_h2);  // kernel 8

    // edge scoring
    sab_kernel<<<(N_NODES + 255) / 256, 256>>>(Wlin);           // kernel 9
    edge_kernel<<<E4B, 256>>>(ei, blin, out);                   // kernel 10
}